// round 1
// baseline (speedup 1.0000x reference)
#include <cuda_runtime.h>
#include <cuda_bf16.h>
#include <math.h>

// Problem constants
#define BATCH 8
#define SEQ   8192
#define DIM   512
#define HEADS 8
#define DH    64
#define SL    32
#define MTOT  (BATCH * SEQ)          // 65536 rows
#define KV_SPLITS 64                 // N-splits for kv reduction

// ---------------- device scratch (no allocations allowed) ----------------
__device__ float g_xmid[(size_t)MTOT * DIM];                 // 134 MB
__device__ float g_u   [(size_t)MTOT * DIM];                 // 134 MB
__device__ float g_S1p [(size_t)KV_SPLITS * 64 * SL * DH];   // split partials: [split][bh][32*64]
__device__ float g_S0p [(size_t)KV_SPLITS * 64 * SL];        // [split][bh][32]
__device__ float g_kv  [(size_t)64 * SL * DH];               // [bh][32*64]

// ---------------- Kernel 1/5: SGEMM  C[M,512] = A[M,512] @ W[512,512] + bias ----------------
// 128x128 block tile, BK=8, 256 threads, 8x8 per thread.
__global__ __launch_bounds__(256) void sgemm_bias_kernel(
    const float* __restrict__ A, const float* __restrict__ W,
    const float* __restrict__ bias, float* __restrict__ C)
{
    const int K = 512, N = 512;
    __shared__ float As[8][128];
    __shared__ float Bs[8][128];

    const int tid = threadIdx.x;
    const int rowBase = blockIdx.y * 128;
    const int colBase = blockIdx.x * 128;

    const int aRow  = tid >> 1;          // 0..127
    const int aCol4 = (tid & 1) * 4;     // 0 or 4
    const int bRow  = tid >> 5;          // 0..7
    const int bCol4 = (tid & 31) * 4;    // 0..124

    const int tr = (tid >> 4) * 8;       // output row offset in tile
    const int tc = (tid & 15) * 8;       // output col offset in tile

    float acc[8][8];
#pragma unroll
    for (int i = 0; i < 8; i++)
#pragma unroll
        for (int j = 0; j < 8; j++) acc[i][j] = 0.f;

    const float* Aptr = A + (size_t)(rowBase + aRow) * K + aCol4;
    const float* Bptr = W + (size_t)bRow * N + colBase + bCol4;

    for (int kt = 0; kt < K; kt += 8) {
        float4 a = *reinterpret_cast<const float4*>(Aptr + kt);
        float4 b = *reinterpret_cast<const float4*>(Bptr + (size_t)kt * N);
        As[aCol4 + 0][aRow] = a.x;
        As[aCol4 + 1][aRow] = a.y;
        As[aCol4 + 2][aRow] = a.z;
        As[aCol4 + 3][aRow] = a.w;
        *reinterpret_cast<float4*>(&Bs[bRow][bCol4]) = b;
        __syncthreads();

#pragma unroll
        for (int k = 0; k < 8; k++) {
            float ra[8], rb[8];
            *reinterpret_cast<float4*>(ra)     = *reinterpret_cast<const float4*>(&As[k][tr]);
            *reinterpret_cast<float4*>(ra + 4) = *reinterpret_cast<const float4*>(&As[k][tr + 4]);
            *reinterpret_cast<float4*>(rb)     = *reinterpret_cast<const float4*>(&Bs[k][tc]);
            *reinterpret_cast<float4*>(rb + 4) = *reinterpret_cast<const float4*>(&Bs[k][tc + 4]);
#pragma unroll
            for (int i = 0; i < 8; i++)
#pragma unroll
                for (int j = 0; j < 8; j++)
                    acc[i][j] = fmaf(ra[i], rb[j], acc[i][j]);
        }
        __syncthreads();
    }

    float bs[8];
#pragma unroll
    for (int j = 0; j < 8; j++) bs[j] = bias[colBase + tc + j];

#pragma unroll
    for (int i = 0; i < 8; i++) {
        float* cp = C + (size_t)(rowBase + tr + i) * N + colBase + tc;
        float4 o0, o1;
        o0.x = acc[i][0] + bs[0]; o0.y = acc[i][1] + bs[1];
        o0.z = acc[i][2] + bs[2]; o0.w = acc[i][3] + bs[3];
        o1.x = acc[i][4] + bs[4]; o1.y = acc[i][5] + bs[5];
        o1.z = acc[i][6] + bs[6]; o1.w = acc[i][7] + bs[7];
        *reinterpret_cast<float4*>(cp)     = o0;
        *reinterpret_cast<float4*>(cp + 4) = o1;
    }
}

// ---------------- Kernel 2: kv accumulate ----------------
// grid (KV_SPLITS, HEADS, BATCH), 256 threads. Each block: 128 tokens in 4 chunks of 32.
// Computes k = exp(x_h @ Wk), v = x_h @ Wv; accumulates S1[s,c] += k_s * v_c, S0[s] += k_s.
// Writes per-split partials (no atomics -> deterministic).
__global__ __launch_bounds__(256) void kv_accum_kernel(
    const float* __restrict__ xmid, const float* __restrict__ Wk,
    const float* __restrict__ Wv)
{
    const int split = blockIdx.x;
    const int h = blockIdx.y;
    const int b = blockIdx.z;
    const int bh = b * HEADS + h;
    const int tid = threadIdx.x;

    __shared__ float Wks[64][32];
    __shared__ float Wvs[64][64];
    __shared__ float Xs[32][65];
    __shared__ float Es[32][33];
    __shared__ float Vs[32][65];

    for (int idx = tid; idx < 64 * 32; idx += 256) Wks[idx >> 5][idx & 31] = Wk[idx];
    for (int idx = tid; idx < 64 * 64; idx += 256) Wvs[idx >> 6][idx & 63] = Wv[idx];

    const int s_own = tid >> 3;          // s index owned (0..31)
    const int c_own = (tid & 7) * 8;     // c base owned
    float acc[8];
#pragma unroll
    for (int i = 0; i < 8; i++) acc[i] = 0.f;
    float s0acc = 0.f;

    for (int chunk = 0; chunk < 4; chunk++) {
        const int n0 = split * 128 + chunk * 32;
        __syncthreads();  // protect Xs (vs prev dot phase) and Es/Vs (vs prev accumulate)

        for (int idx = tid; idx < 32 * 64; idx += 256) {
            int r = idx >> 6, c = idx & 63;
            Xs[r][c] = xmid[(size_t)(b * SEQ + n0 + r) * DIM + h * DH + c];
        }
        __syncthreads();

        for (int idx = tid; idx < 32 * 96; idx += 256) {
            int r = idx / 96;
            int j = idx - r * 96;
            float d = 0.f;
            if (j < 32) {
#pragma unroll
                for (int t = 0; t < 64; t++) d = fmaf(Xs[r][t], Wks[t][j], d);
                Es[r][j] = expf(d);
            } else {
                int c = j - 32;
#pragma unroll
                for (int t = 0; t < 64; t++) d = fmaf(Xs[r][t], Wvs[t][c], d);
                Vs[r][c] = d;
            }
        }
        __syncthreads();

#pragma unroll 4
        for (int r = 0; r < 32; r++) {
            float e = Es[r][s_own];
            const float* vp = &Vs[r][c_own];
#pragma unroll
            for (int i = 0; i < 8; i++) acc[i] = fmaf(e, vp[i], acc[i]);
        }
        if (tid < 32) {
#pragma unroll 4
            for (int r = 0; r < 32; r++) s0acc += Es[r][tid];
        }
    }

    float* s1p = g_S1p + ((size_t)split * 64 + bh) * (SL * DH) + tid * 8;
#pragma unroll
    for (int i = 0; i < 8; i++) s1p[i] = acc[i];
    if (tid < 32) g_S0p[((size_t)split * 64 + bh) * SL + tid] = s0acc;
}

// ---------------- Kernel 3: kv finalize (deterministic split reduction + divide) ----------------
__global__ __launch_bounds__(256) void kv_final_kernel()
{
    int idx = blockIdx.x * 256 + threadIdx.x;   // over 64 * 2048
    if (idx >= 64 * SL * DH) return;
    int bh = idx >> 11;
    int sc = idx & 2047;
    int s  = sc >> 6;
    float s1 = 0.f, s0 = 0.f;
    for (int sp = 0; sp < KV_SPLITS; sp++) {
        s1 += g_S1p[((size_t)sp * 64 + bh) * (SL * DH) + sc];
        s0 += g_S0p[((size_t)sp * 64 + bh) * SL + s];
    }
    g_kv[idx] = s1 / s0;
}

// ---------------- Kernel 4: q projection + softmax(slice) + q @ kv -> u ----------------
// grid (128 tiles of 64 tokens, HEADS, BATCH), 128 threads.
__global__ __launch_bounds__(128) void qkv_kernel(
    const float* __restrict__ xmid, const float* __restrict__ Wq)
{
    const int tile = blockIdx.x;
    const int h = blockIdx.y;
    const int b = blockIdx.z;
    const int bh = b * HEADS + h;
    const int tid = threadIdx.x;
    const int n0 = tile * 64;

    __shared__ float Wqs[64][32];
    __shared__ float kvs[32][64];
    __shared__ float Xs[64][65];
    __shared__ float Qs[64][33];

    for (int idx = tid; idx < 64 * 32; idx += 128) Wqs[idx >> 5][idx & 31] = Wq[idx];
    for (int idx = tid; idx < SL * DH; idx += 128) kvs[idx >> 6][idx & 63] = g_kv[(size_t)bh * (SL * DH) + idx];
    for (int idx = tid; idx < 64 * 64; idx += 128) {
        int r = idx >> 6, c = idx & 63;
        Xs[r][c] = xmid[(size_t)(b * SEQ + n0 + r) * DIM + h * DH + c];
    }
    __syncthreads();

    // q dots: 64 tokens x 32 slices, flat over 128 threads
    for (int idx = tid; idx < 64 * 32; idx += 128) {
        int r = idx >> 5, s = idx & 31;
        float d = 0.f;
#pragma unroll
        for (int t = 0; t < 64; t++) d = fmaf(Xs[r][t], Wqs[t][s], d);
        Qs[r][s] = d;
    }
    __syncthreads();

    // softmax over slice dim, one token per thread (tid < 64)
    if (tid < 64) {
        float m = Qs[tid][0];
#pragma unroll
        for (int s = 1; s < 32; s++) m = fmaxf(m, Qs[tid][s]);
        float sum = 0.f;
        float e[32];
#pragma unroll
        for (int s = 0; s < 32; s++) { e[s] = expf(Qs[tid][s] - m); sum += e[s]; }
        float inv = 1.f / sum;
#pragma unroll
        for (int s = 0; s < 32; s++) Qs[tid][s] = e[s] * inv;
    }
    __syncthreads();

    // out dots: 64 tokens x 64 channels, flat -> coalesced global write
    for (int idx = tid; idx < 64 * 64; idx += 128) {
        int r = idx >> 6, c = idx & 63;
        float d = 0.f;
#pragma unroll
        for (int s = 0; s < 32; s++) d = fmaf(Qs[r][s], kvs[s][c], d);
        g_u[(size_t)(b * SEQ + n0 + r) * DIM + h * DH + c] = d;
    }
}

// ---------------- launch ----------------
extern "C" void kernel_launch(void* const* d_in, const int* in_sizes, int n_in,
                              void* d_out, int out_size)
{
    const float* x     = (const float*)d_in[0];
    const float* W_in  = (const float*)d_in[1];
    const float* b_in  = (const float*)d_in[2];
    const float* Wq    = (const float*)d_in[3];
    const float* Wk    = (const float*)d_in[4];
    const float* Wv    = (const float*)d_in[5];
    const float* W_out = (const float*)d_in[6];
    const float* b_out = (const float*)d_in[7];
    float* out = (float*)d_out;

    float *xmid, *u;
    cudaGetSymbolAddress((void**)&xmid, g_xmid);
    cudaGetSymbolAddress((void**)&u, g_u);

    dim3 gemmGrid(DIM / 128, MTOT / 128);

    // 1) x_mid = x @ W_in + b_in
    sgemm_bias_kernel<<<gemmGrid, 256>>>(x, W_in, b_in, xmid);

    // 2) kv split partials
    dim3 kvGrid(KV_SPLITS, HEADS, BATCH);
    kv_accum_kernel<<<kvGrid, 256>>>(xmid, Wk, Wv);

    // 3) kv finalize
    kv_final_kernel<<<(64 * SL * DH + 255) / 256, 256>>>();

    // 4) q softmax + q @ kv -> u
    dim3 qGrid(SEQ / 64, HEADS, BATCH);
    qkv_kernel<<<qGrid, 128>>>(xmid, Wq);

    // 5) out = u @ W_out + b_out
    sgemm_bias_kernel<<<gemmGrid, 256>>>(u, W_out, b_out, out);
}

// round 2
// speedup vs baseline: 1.5838x; 1.5838x over previous
#include <cuda_runtime.h>
#include <cuda_bf16.h>
#include <math.h>

// Problem constants
#define BATCH 8
#define SEQ   8192
#define DIM   512
#define HEADS 8
#define DH    64
#define SL    32
#define MTOT  (BATCH * SEQ)          // 65536 rows
#define KV_SPLITS 64                 // N-splits for kv reduction

// ---------------- device scratch (no allocations allowed) ----------------
__device__ float g_xmid[(size_t)MTOT * DIM];                 // 134 MB
__device__ float g_u   [(size_t)MTOT * DIM];                 // 134 MB
__device__ float g_S1p [(size_t)KV_SPLITS * 64 * SL * DH];   // split partials
__device__ float g_S0p [(size_t)KV_SPLITS * 64 * SL];
__device__ float g_kv  [(size_t)64 * SL * DH];

__device__ __forceinline__ unsigned f2tf32(float f) {
    unsigned u;
    asm("cvt.rna.tf32.f32 %0, %1;" : "=r"(u) : "f"(f));
    return u;
}

// ---------------- Kernel 1/5: TF32 tensor-core GEMM  C[M,512] = A[M,512] @ W[512,512] + bias
// 128x128 block tile, BK=16, 256 threads (8 warps), warp tile 32x64 via m16n8k8 tf32 mma.
__global__ __launch_bounds__(256) void tf32gemm_bias_kernel(
    const float* __restrict__ A, const float* __restrict__ W,
    const float* __restrict__ bias, float* __restrict__ C)
{
    const int K = 512, N = 512;
    // Padded strides chosen so fragment LDS patterns are bank-conflict-free:
    // A stride 20: banks (r*20 + c) % 32 distinct for r in 0..7, c in 0..3 (+4,+8 shifts).
    // B stride 136: banks (r*136 + c) % 32 = (r*8 + c) % 32 distinct for r in 0..3, c in 0..7.
    __shared__ float As[128][20];
    __shared__ float Bs[16][136];

    const int tid  = threadIdx.x;
    const int warp = tid >> 5;
    const int lane = tid & 31;
    const int g = lane >> 2;     // group id 0..7
    const int t = lane & 3;      // thread-in-group 0..3

    const int rowBase = blockIdx.y * 128;
    const int colBase = blockIdx.x * 128;
    const int wm = (warp & 3) * 32;   // warp row offset in tile
    const int wn = (warp >> 2) * 64;  // warp col offset in tile

    float acc[2][8][4];
#pragma unroll
    for (int mt = 0; mt < 2; mt++)
#pragma unroll
        for (int nt = 0; nt < 8; nt++)
#pragma unroll
            for (int i = 0; i < 4; i++) acc[mt][nt][i] = 0.f;

    // Global load mapping (per ktile): A 128x16 = 512 float4; B 16x128 = 512 float4.
    const int aRow0 = tid >> 2;             // rows for idx=tid
    const int aC4   = (tid & 3) * 4;
    const int aRow1 = (tid + 256) >> 2;     // rows for idx=tid+256
    const int bRow0 = tid >> 5;             // 0..7
    const int bC4   = (tid & 31) * 4;
    const int bRow1 = (tid + 256) >> 5;     // 8..15

    for (int kt = 0; kt < K; kt += 16) {
        // ---- global -> regs ----
        float4 a0 = *reinterpret_cast<const float4*>(&A[(size_t)(rowBase + aRow0) * K + kt + aC4]);
        float4 a1 = *reinterpret_cast<const float4*>(&A[(size_t)(rowBase + aRow1) * K + kt + aC4]);
        float4 b0 = *reinterpret_cast<const float4*>(&W[(size_t)(kt + bRow0) * N + colBase + bC4]);
        float4 b1 = *reinterpret_cast<const float4*>(&W[(size_t)(kt + bRow1) * N + colBase + bC4]);

        __syncthreads();   // previous tile's compute done before overwrite

        // ---- regs -> smem (with tf32 rounding) ----
        As[aRow0][aC4 + 0] = __uint_as_float(f2tf32(a0.x));
        As[aRow0][aC4 + 1] = __uint_as_float(f2tf32(a0.y));
        As[aRow0][aC4 + 2] = __uint_as_float(f2tf32(a0.z));
        As[aRow0][aC4 + 3] = __uint_as_float(f2tf32(a0.w));
        As[aRow1][aC4 + 0] = __uint_as_float(f2tf32(a1.x));
        As[aRow1][aC4 + 1] = __uint_as_float(f2tf32(a1.y));
        As[aRow1][aC4 + 2] = __uint_as_float(f2tf32(a1.z));
        As[aRow1][aC4 + 3] = __uint_as_float(f2tf32(a1.w));
        float4 tb0, tb1;
        tb0.x = __uint_as_float(f2tf32(b0.x)); tb0.y = __uint_as_float(f2tf32(b0.y));
        tb0.z = __uint_as_float(f2tf32(b0.z)); tb0.w = __uint_as_float(f2tf32(b0.w));
        tb1.x = __uint_as_float(f2tf32(b1.x)); tb1.y = __uint_as_float(f2tf32(b1.y));
        tb1.z = __uint_as_float(f2tf32(b1.z)); tb1.w = __uint_as_float(f2tf32(b1.w));
        *reinterpret_cast<float4*>(&Bs[bRow0][bC4]) = tb0;
        *reinterpret_cast<float4*>(&Bs[bRow1][bC4]) = tb1;

        __syncthreads();

        // ---- compute: 2 k-steps of 8 ----
#pragma unroll
        for (int ks = 0; ks < 16; ks += 8) {
            unsigned af[2][4];
#pragma unroll
            for (int mt = 0; mt < 2; mt++) {
                const int r0 = wm + mt * 16 + g;
                af[mt][0] = __float_as_uint(As[r0    ][ks + t    ]);
                af[mt][1] = __float_as_uint(As[r0 + 8][ks + t    ]);
                af[mt][2] = __float_as_uint(As[r0    ][ks + t + 4]);
                af[mt][3] = __float_as_uint(As[r0 + 8][ks + t + 4]);
            }
            unsigned bf[8][2];
#pragma unroll
            for (int nt = 0; nt < 8; nt++) {
                const int c0 = wn + nt * 8 + g;
                bf[nt][0] = __float_as_uint(Bs[ks + t    ][c0]);
                bf[nt][1] = __float_as_uint(Bs[ks + t + 4][c0]);
            }
#pragma unroll
            for (int mt = 0; mt < 2; mt++)
#pragma unroll
                for (int nt = 0; nt < 8; nt++) {
                    asm volatile(
                        "mma.sync.aligned.m16n8k8.row.col.f32.tf32.tf32.f32 "
                        "{%0,%1,%2,%3}, {%4,%5,%6,%7}, {%8,%9}, {%0,%1,%2,%3};"
                        : "+f"(acc[mt][nt][0]), "+f"(acc[mt][nt][1]),
                          "+f"(acc[mt][nt][2]), "+f"(acc[mt][nt][3])
                        : "r"(af[mt][0]), "r"(af[mt][1]), "r"(af[mt][2]), "r"(af[mt][3]),
                          "r"(bf[nt][0]), "r"(bf[nt][1]));
                }
        }
        __syncthreads();
    }

    // ---- epilogue: bias + store ----
#pragma unroll
    for (int nt = 0; nt < 8; nt++) {
        const int col = colBase + wn + nt * 8 + 2 * t;
        const float bx = bias[col], by = bias[col + 1];
#pragma unroll
        for (int mt = 0; mt < 2; mt++) {
            const int row0 = rowBase + wm + mt * 16 + g;
            float2 o0, o1;
            o0.x = acc[mt][nt][0] + bx; o0.y = acc[mt][nt][1] + by;
            o1.x = acc[mt][nt][2] + bx; o1.y = acc[mt][nt][3] + by;
            *reinterpret_cast<float2*>(&C[(size_t)row0 * N + col])       = o0;
            *reinterpret_cast<float2*>(&C[(size_t)(row0 + 8) * N + col]) = o1;
        }
    }
}

// ---------------- Kernel 2: kv accumulate ----------------
__global__ __launch_bounds__(256) void kv_accum_kernel(
    const float* __restrict__ xmid, const float* __restrict__ Wk,
    const float* __restrict__ Wv)
{
    const int split = blockIdx.x;
    const int h = blockIdx.y;
    const int b = blockIdx.z;
    const int bh = b * HEADS + h;
    const int tid = threadIdx.x;

    __shared__ float Wks[64][32];
    __shared__ float Wvs[64][64];
    __shared__ float Xs[32][65];
    __shared__ float Es[32][33];
    __shared__ float Vs[32][65];

    for (int idx = tid; idx < 64 * 32; idx += 256) Wks[idx >> 5][idx & 31] = Wk[idx];
    for (int idx = tid; idx < 64 * 64; idx += 256) Wvs[idx >> 6][idx & 63] = Wv[idx];

    const int s_own = tid >> 3;
    const int c_own = (tid & 7) * 8;
    float acc[8];
#pragma unroll
    for (int i = 0; i < 8; i++) acc[i] = 0.f;
    float s0acc = 0.f;

    for (int chunk = 0; chunk < 4; chunk++) {
        const int n0 = split * 128 + chunk * 32;
        __syncthreads();

        for (int idx = tid; idx < 32 * 64; idx += 256) {
            int r = idx >> 6, c = idx & 63;
            Xs[r][c] = xmid[(size_t)(b * SEQ + n0 + r) * DIM + h * DH + c];
        }
        __syncthreads();

        for (int idx = tid; idx < 32 * 96; idx += 256) {
            int r = idx / 96;
            int j = idx - r * 96;
            float d = 0.f;
            if (j < 32) {
#pragma unroll
                for (int t = 0; t < 64; t++) d = fmaf(Xs[r][t], Wks[t][j], d);
                Es[r][j] = expf(d);
            } else {
                int c = j - 32;
#pragma unroll
                for (int t = 0; t < 64; t++) d = fmaf(Xs[r][t], Wvs[t][c], d);
                Vs[r][c] = d;
            }
        }
        __syncthreads();

#pragma unroll 4
        for (int r = 0; r < 32; r++) {
            float e = Es[r][s_own];
            const float* vp = &Vs[r][c_own];
#pragma unroll
            for (int i = 0; i < 8; i++) acc[i] = fmaf(e, vp[i], acc[i]);
        }
        if (tid < 32) {
#pragma unroll 4
            for (int r = 0; r < 32; r++) s0acc += Es[r][tid];
        }
    }

    float* s1p = g_S1p + ((size_t)split * 64 + bh) * (SL * DH) + tid * 8;
#pragma unroll
    for (int i = 0; i < 8; i++) s1p[i] = acc[i];
    if (tid < 32) g_S0p[((size_t)split * 64 + bh) * SL + tid] = s0acc;
}

// ---------------- Kernel 3: kv finalize ----------------
__global__ __launch_bounds__(256) void kv_final_kernel()
{
    int idx = blockIdx.x * 256 + threadIdx.x;
    if (idx >= 64 * SL * DH) return;
    int bh = idx >> 11;
    int sc = idx & 2047;
    int s  = sc >> 6;
    float s1 = 0.f, s0 = 0.f;
    for (int sp = 0; sp < KV_SPLITS; sp++) {
        s1 += g_S1p[((size_t)sp * 64 + bh) * (SL * DH) + sc];
        s0 += g_S0p[((size_t)sp * 64 + bh) * SL + s];
    }
    g_kv[idx] = s1 / s0;
}

// ---------------- Kernel 4: q projection + softmax(slice) + q @ kv -> u ----------------
__global__ __launch_bounds__(128) void qkv_kernel(
    const float* __restrict__ xmid, const float* __restrict__ Wq)
{
    const int tile = blockIdx.x;
    const int h = blockIdx.y;
    const int b = blockIdx.z;
    const int bh = b * HEADS + h;
    const int tid = threadIdx.x;
    const int n0 = tile * 64;

    __shared__ float Wqs[64][32];
    __shared__ float kvs[32][64];
    __shared__ float Xs[64][65];
    __shared__ float Qs[64][33];

    for (int idx = tid; idx < 64 * 32; idx += 128) Wqs[idx >> 5][idx & 31] = Wq[idx];
    for (int idx = tid; idx < SL * DH; idx += 128) kvs[idx >> 6][idx & 63] = g_kv[(size_t)bh * (SL * DH) + idx];
    for (int idx = tid; idx < 64 * 64; idx += 128) {
        int r = idx >> 6, c = idx & 63;
        Xs[r][c] = xmid[(size_t)(b * SEQ + n0 + r) * DIM + h * DH + c];
    }
    __syncthreads();

    for (int idx = tid; idx < 64 * 32; idx += 128) {
        int r = idx >> 5, s = idx & 31;
        float d = 0.f;
#pragma unroll
        for (int t = 0; t < 64; t++) d = fmaf(Xs[r][t], Wqs[t][s], d);
        Qs[r][s] = d;
    }
    __syncthreads();

    if (tid < 64) {
        float m = Qs[tid][0];
#pragma unroll
        for (int s = 1; s < 32; s++) m = fmaxf(m, Qs[tid][s]);
        float sum = 0.f;
        float e[32];
#pragma unroll
        for (int s = 0; s < 32; s++) { e[s] = expf(Qs[tid][s] - m); sum += e[s]; }
        float inv = 1.f / sum;
#pragma unroll
        for (int s = 0; s < 32; s++) Qs[tid][s] = e[s] * inv;
    }
    __syncthreads();

    for (int idx = tid; idx < 64 * 64; idx += 128) {
        int r = idx >> 6, c = idx & 63;
        float d = 0.f;
#pragma unroll
        for (int s = 0; s < 32; s++) d = fmaf(Qs[r][s], kvs[s][c], d);
        g_u[(size_t)(b * SEQ + n0 + r) * DIM + h * DH + c] = d;
    }
}

// ---------------- launch ----------------
extern "C" void kernel_launch(void* const* d_in, const int* in_sizes, int n_in,
                              void* d_out, int out_size)
{
    const float* x     = (const float*)d_in[0];
    const float* W_in  = (const float*)d_in[1];
    const float* b_in  = (const float*)d_in[2];
    const float* Wq    = (const float*)d_in[3];
    const float* Wk    = (const float*)d_in[4];
    const float* Wv    = (const float*)d_in[5];
    const float* W_out = (const float*)d_in[6];
    const float* b_out = (const float*)d_in[7];
    float* out = (float*)d_out;

    float *xmid, *u;
    cudaGetSymbolAddress((void**)&xmid, g_xmid);
    cudaGetSymbolAddress((void**)&u, g_u);

    dim3 gemmGrid(DIM / 128, MTOT / 128);

    // 1) x_mid = x @ W_in + b_in   (tf32 tensor cores)
    tf32gemm_bias_kernel<<<gemmGrid, 256>>>(x, W_in, b_in, xmid);

    // 2) kv split partials
    dim3 kvGrid(KV_SPLITS, HEADS, BATCH);
    kv_accum_kernel<<<kvGrid, 256>>>(xmid, Wk, Wv);

    // 3) kv finalize
    kv_final_kernel<<<(64 * SL * DH + 255) / 256, 256>>>();

    // 4) q softmax + q @ kv -> u
    dim3 qGrid(SEQ / 64, HEADS, BATCH);
    qkv_kernel<<<qGrid, 128>>>(xmid, Wq);

    // 5) out = u @ W_out + b_out   (tf32 tensor cores)
    tf32gemm_bias_kernel<<<gemmGrid, 256>>>(u, W_out, b_out, out);
}